// round 14
// baseline (speedup 1.0000x reference)
#include <cuda_runtime.h>
#include <cuda_bf16.h>
#include <cstdint>

typedef unsigned long long ull;
typedef unsigned int uint;

#define BB 16
#define CC 64
#define NN 4096      // H*W
#define NP 1024      // pooled positions
#define L2E 1.4426950408889634f

// ---------------- scratch (device globals; no allocation) ----------------
__device__ __nv_bfloat16 g_theta_b[BB * NN * 8];   // [b][n][8]   bf16, pre-scaled by log2e
__device__ __nv_bfloat16 g_phi_b[BB * NP * 8];     // [b][p][8]   bf16
__device__ __nv_bfloat16 g_gT_b[BB * 32 * NP];     // [b][ch][p]  bf16 (transposed)

// ---------------- f32x2 / misc helpers ----------------
__device__ __forceinline__ ull pack2(float lo, float hi) {
    ull r; asm("mov.b64 %0, {%1,%2};" : "=l"(r) : "f"(lo), "f"(hi)); return r;
}
__device__ __forceinline__ void unpack2(ull v, float& lo, float& hi) {
    asm("mov.b64 {%0,%1}, %2;" : "=f"(lo), "=f"(hi) : "l"(v));
}
__device__ __forceinline__ void fma2(ull& d, ull a, ull b) {
    asm("fma.rn.f32x2 %0, %1, %2, %0;" : "+l"(d) : "l"(a), "l"(b));
}
__device__ __forceinline__ ull mul2(ull a, ull b) {
    ull d; asm("mul.rn.f32x2 %0, %1, %2;" : "=l"(d) : "l"(a), "l"(b)); return d;
}
__device__ __forceinline__ float ex2f(float x) {
    float r; asm("ex2.approx.f32 %0, %1;" : "=f"(r) : "f"(x)); return r;
}
// pack two f32 -> bf16x2 (first arg -> low half)
__device__ __forceinline__ uint bf2(float lo, float hi) {
    uint r; asm("cvt.rn.bf16x2.f32 %0, %1, %2;" : "=r"(r) : "f"(hi), "f"(lo)); return r;
}
__device__ __forceinline__ float shflx(float v, int m) {
    float r; asm("shfl.sync.bfly.b32 %0, %1, %2, 0x1F, 0xFFFFFFFF;" : "=f"(r) : "f"(v), "r"(m));
    return r;
}

// ---------------- mma.sync (base sm_80+ feature; OK on plain sm_100) -----
__device__ __forceinline__ void mma_16n8k8(float d[4], const uint a[2], uint b) {
    asm volatile(
        "mma.sync.aligned.m16n8k8.row.col.f32.bf16.bf16.f32 "
        "{%0,%1,%2,%3}, {%4,%5}, {%6}, {%0,%1,%2,%3};"
        : "+f"(d[0]), "+f"(d[1]), "+f"(d[2]), "+f"(d[3])
        : "r"(a[0]), "r"(a[1]), "r"(b));
}
__device__ __forceinline__ void mma_16n8k16(float d[4], const uint a[4], uint b0, uint b1) {
    asm volatile(
        "mma.sync.aligned.m16n8k16.row.col.f32.bf16.bf16.f32 "
        "{%0,%1,%2,%3}, {%4,%5,%6,%7}, {%8,%9}, {%0,%1,%2,%3};"
        : "+f"(d[0]), "+f"(d[1]), "+f"(d[2]), "+f"(d[3])
        : "r"(a[0]), "r"(a[1]), "r"(a[2]), "r"(a[3]), "r"(b0), "r"(b1));
}

// =========================================================================
// Kernel 1: 1x1 conv projections + 2x2 maxpool -> bf16 outputs.
// 256 threads: thread = (pooled position, dy). Pairs of adjacent lanes
// combine the 2x2 maxpool via shfl.xor 1. dy=0 writes phi, dy=1 writes gT.
// =========================================================================
__global__ void __launch_bounds__(256, 1)
proj_kernel(const float* __restrict__ x,
            const float* __restrict__ tw,
            const float* __restrict__ pw,
            const float* __restrict__ gw)
{
    __shared__ float ws[64 * 48];
    for (int i = threadIdx.x; i < 64 * 48; i += 256) {
        int k = i / 48, o = i % 48;
        float v;
        if (o < 8)        v = tw[o * 64 + k];
        else if (o < 16)  v = pw[(o - 8) * 64 + k];
        else              v = gw[(o - 16) * 64 + k];
        ws[i] = v;
    }
    __syncthreads();

    const int tid = threadIdx.x;
    const int dy  = tid & 1;
    int p  = blockIdx.x * 128 + (tid >> 1);   // global pooled index
    int b  = p >> 10;
    int pp = p & 1023;
    int hp = pp >> 5, wp = pp & 31;

    const float* xb = x + (size_t)b * CC * NN;

    ull acc0[24], acc1[24];
#pragma unroll
    for (int c = 0; c < 24; c++) { acc0[c] = 0ull; acc1[c] = 0ull; }

    const float* xrow = xb + (2 * hp + dy) * 64 + 2 * wp;
#pragma unroll 4
    for (int k = 0; k < 64; k++) {
        float2 xv = *(const float2*)(xrow + (size_t)k * NN);
        ull a0 = pack2(xv.x, xv.x);
        ull a1 = pack2(xv.y, xv.y);
        const ull* w2 = (const ull*)(ws + k * 48);
#pragma unroll
        for (int c = 0; c < 24; c++) {
            ull w = w2[c];
            fma2(acc0[c], a0, w);
            fma2(acc1[c], a1, w);
        }
    }

    // theta write (this thread's row: 2 pixels), bf16 pre-scaled by log2(e)
    {
        int n0 = (2 * hp + dy) * 64 + 2 * wp;
        float u, v; uint4 q;
        unpack2(acc0[0], u, v); q.x = bf2(u * L2E, v * L2E);
        unpack2(acc0[1], u, v); q.y = bf2(u * L2E, v * L2E);
        unpack2(acc0[2], u, v); q.z = bf2(u * L2E, v * L2E);
        unpack2(acc0[3], u, v); q.w = bf2(u * L2E, v * L2E);
        *(uint4*)(g_theta_b + ((size_t)b * NN + n0) * 8) = q;
        unpack2(acc1[0], u, v); q.x = bf2(u * L2E, v * L2E);
        unpack2(acc1[1], u, v); q.y = bf2(u * L2E, v * L2E);
        unpack2(acc1[2], u, v); q.z = bf2(u * L2E, v * L2E);
        unpack2(acc1[3], u, v); q.w = bf2(u * L2E, v * L2E);
        *(uint4*)(g_theta_b + ((size_t)b * NN + n0 + 1) * 8) = q;
    }

    // pool within this row (2 pixels) -> best[40], then combine with partner
    float best[40];
#pragma unroll
    for (int c = 4; c < 24; c++) {
        float u0, v0, u1, v1;
        unpack2(acc0[c], u0, v0);
        unpack2(acc1[c], u1, v1);
        best[2 * c - 8]     = fmaxf(u0, u1);
        best[2 * c - 8 + 1] = fmaxf(v0, v1);
    }
#pragma unroll
    for (int c = 0; c < 40; c++)
        best[c] = fmaxf(best[c], shflx(best[c], 1));   // dy-partner = lane^1

    if (dy == 0) {   // phi bf16 [b][pp][8]
        uint4 q;
        q.x = bf2(best[0], best[1]); q.y = bf2(best[2], best[3]);
        q.z = bf2(best[4], best[5]); q.w = bf2(best[6], best[7]);
        *(uint4*)(g_phi_b + ((size_t)b * NP + pp) * 8) = q;
    } else {         // g transposed bf16 [b][ch][pp]
#pragma unroll
        for (int c = 0; c < 32; c++)
            g_gT_b[((size_t)b * 32 + c) * NP + pp] = __float2bfloat16(best[8 + c]);
    }
}

// =========================================================================
// Kernel 2: mma.sync flash attention + o-projection + residual.
// Grid (8 tiles, 16 batches), 1024 threads (32 warps = 8/SMSP).
// Warp owns 16 queries (one m16 tile) -> ~50 regs/thread, full residency.
// Epilogue: 2 threads per query, 32 o_w rows each.
// =========================================================================
#define THREADS 1024
#define SM_PHI   0                    // 1024 x 16B bf16        = 16384
#define SM_GB    16384                // 64kc x 4nt x 32 x 8B   = 65536
#define SM_OW    (16384 + 65536)      // 64 x 32 f32            = 8192
#define SM_DEN   (16384 + 65536 + 8192)            // 512 f32   = 2048
#define SM_ATT   (16384 + 65536 + 8192 + 2048)     // 512 x 34 f32 = 69632
#define SMEM_BYTES (16384 + 65536 + 8192 + 2048 + 69632)
#define ATT_STRIDE 34

__global__ void __launch_bounds__(THREADS, 1)
attn_kernel(const float* __restrict__ x,
            const float* __restrict__ ow,
            const float* __restrict__ gamma_p,
            float* __restrict__ out)
{
    extern __shared__ char sm[];
    const int tid  = threadIdx.x;
    const int wid  = tid >> 5;
    const int lane = tid & 31;
    const int g    = lane >> 2;      // groupID
    const int tig  = lane & 3;       // thread-in-group
    const int b    = blockIdx.y;
    const int tile = blockIdx.x;

    // ---- stage phi [key][8ch] bf16 ----
    {
        const uint4* src = (const uint4*)(g_phi_b + (size_t)b * NP * 8);
        uint4* dst = (uint4*)(sm + SM_PHI);
        for (int i = tid; i < 1024; i += THREADS) dst[i] = src[i];
    }
    // ---- stage gB in b-frag order: [kc][nt][lane] = (b0|b1<<32) ----
    {
        const __nv_bfloat16* gT = g_gT_b + (size_t)b * 32 * NP;
        ull* dst = (ull*)(sm + SM_GB);
        for (int idx = tid; idx < 64 * 4 * 32; idx += THREADS) {
            int ln = idx & 31, nt = (idx >> 5) & 3, kc = idx >> 7;
            int ch = nt * 8 + (ln >> 2);
            const __nv_bfloat16* row = gT + (size_t)ch * NP + kc * 16 + 2 * (ln & 3);
            uint lo = *(const uint*)row;        // keys 2tig, 2tig+1
            uint hi = *(const uint*)(row + 8);  // keys 2tig+8, 2tig+9
            dst[idx] = (ull)lo | ((ull)hi << 32);
        }
    }
    // ---- stage ow (f32) ----
    {
        const float4* src = (const float4*)ow;
        float4* dst = (float4*)(sm + SM_OW);
        for (int i = tid; i < 512; i += THREADS) dst[i] = src[i];
    }
    __syncthreads();

    // ---- theta a-frag: warp's single 16-row q-tile ----
    const int wq = tile * 512 + wid * 16;      // warp's first query (global n)
    uint ta[2];
    {
        const __nv_bfloat16* t0 = g_theta_b + ((size_t)b * NN + wq + g) * 8 + 2 * tig;
        ta[0] = *(const uint*)t0;
        ta[1] = *(const uint*)(t0 + 64);       // row +8 -> +8*8 elements
    }

    float aoc[4][4];
#pragma unroll
    for (int nt = 0; nt < 4; nt++)
#pragma unroll
        for (int r = 0; r < 4; r++) aoc[nt][r] = 0.f;
    float dn0 = 0.f, dn1 = 0.f;

    // running pointers (strength-reduced addressing)
    const char* phiP = sm + SM_PHI + g * 16 + tig * 4;   // +256 B per kc
    const ull*  gP   = (const ull*)(sm + SM_GB) + lane;  // +128 ull per kc

#pragma unroll 2
    for (int kc = 0; kc < 64; kc++) {
        uint pb0 = *(const uint*)phiP;
        uint pb1 = *(const uint*)(phiP + 128);
        ull gv0 = gP[0], gv1 = gP[32], gv2 = gP[64], gv3 = gP[96];
        phiP += 256; gP += 128;

        uint pa[4];
        {
            float s[4] = {0.f, 0.f, 0.f, 0.f};
            mma_16n8k8(s, ta, pb0);
            float e0 = ex2f(s[0]), e1 = ex2f(s[1]);
            float e2 = ex2f(s[2]), e3 = ex2f(s[3]);
            dn0 += e0 + e1;
            dn1 += e2 + e3;
            pa[0] = bf2(e0, e1);   // (q=g,   k=2tig..+1)
            pa[1] = bf2(e2, e3);   // (q=g+8, k=2tig..+1)
        }
        {
            float s[4] = {0.f, 0.f, 0.f, 0.f};
            mma_16n8k8(s, ta, pb1);
            float e0 = ex2f(s[0]), e1 = ex2f(s[1]);
            float e2 = ex2f(s[2]), e3 = ex2f(s[3]);
            dn0 += e0 + e1;
            dn1 += e2 + e3;
            pa[2] = bf2(e0, e1);
            pa[3] = bf2(e2, e3);
        }
        // GEMM2: A += P x gT
        mma_16n8k16(aoc[0], pa, (uint)gv0, (uint)(gv0 >> 32));
        mma_16n8k16(aoc[1], pa, (uint)gv1, (uint)(gv1 >> 32));
        mma_16n8k16(aoc[2], pa, (uint)gv2, (uint)(gv2 >> 32));
        mma_16n8k16(aoc[3], pa, (uint)gv3, (uint)(gv3 >> 32));
    }

    // ---- den reduce (over tig lanes) + store attn/den to smem ----
    float* denS = (float*)(sm + SM_DEN);
    float* attS = (float*)(sm + SM_ATT);
    const int wqp = wid * 16;                  // warp's query offset within tile
    {
        float d0 = dn0; d0 += shflx(d0, 1); d0 += shflx(d0, 2);
        float d1 = dn1; d1 += shflx(d1, 1); d1 += shflx(d1, 2);
        if (tig == 0) {
            denS[wqp + g]     = d0;
            denS[wqp + g + 8] = d1;
        }
#pragma unroll
        for (int nt = 0; nt < 4; nt++) {
            int q0 = wqp + g;
            int ch = nt * 8 + 2 * tig;
            *(float2*)(attS + (size_t)q0 * ATT_STRIDE + ch) =
                make_float2(aoc[nt][0], aoc[nt][1]);
            *(float2*)(attS + (size_t)(q0 + 8) * ATT_STRIDE + ch) =
                make_float2(aoc[nt][2], aoc[nt][3]);
        }
    }
    __syncthreads();

    // ---- epilogue: 2 threads per query, 32 o_w rows each ----
    const float gamma = *gamma_p;
    const ulonglong2* ow4 = (const ulonglong2*)(sm + SM_OW);   // [j][8]
    {
        const int p  = tid >> 1;                    // query within tile [0,512)
        const int jh = tid & 1;                     // o_w row half
        ull am[16];
        const ull* ap = (const ull*)(attS + (size_t)p * ATT_STRIDE);
#pragma unroll
        for (int c = 0; c < 16; c++) am[c] = ap[c];
        const float sc = gamma / denS[p];

        const int q = tile * 512 + p;
        const float* xq = x + (size_t)b * CC * NN + q;
        float*       oq = out + (size_t)b * CC * NN + q;
        const int j0 = jh * 32;
        for (int j = j0; j < j0 + 32; j++) {
            const ulonglong2* wj = ow4 + j * 8;
            ulonglong2 w0 = wj[0];
            ull o2 = mul2(w0.x, am[0]);
            fma2(o2, w0.y, am[1]);
#pragma unroll
            for (int k = 1; k < 8; k++) {
                ulonglong2 wk = wj[k];
                fma2(o2, wk.x, am[2 * k]);
                fma2(o2, wk.y, am[2 * k + 1]);
            }
            float oa, ob;
            unpack2(o2, oa, ob);
            oq[(size_t)j * NN] = fmaf(sc, oa + ob, xq[(size_t)j * NN]);
        }
    }
}

// =========================================================================
extern "C" void kernel_launch(void* const* d_in, const int* in_sizes, int n_in,
                              void* d_out, int out_size)
{
    const float* x     = (const float*)d_in[0];
    const float* tw    = (const float*)d_in[1];
    const float* pw    = (const float*)d_in[2];
    const float* gw    = (const float*)d_in[3];
    const float* ow    = (const float*)d_in[4];
    const float* gamma = (const float*)d_in[5];
    float* out = (float*)d_out;

    cudaFuncSetAttribute(attn_kernel,
                         cudaFuncAttributeMaxDynamicSharedMemorySize, SMEM_BYTES);

    proj_kernel<<<BB * NP / 128, 256>>>(x, tw, pw, gw);
    attn_kernel<<<dim3(8, BB), THREADS, SMEM_BYTES>>>(x, ow, gamma, out);
}

// round 15
// speedup vs baseline: 1.2512x; 1.2512x over previous
#include <cuda_runtime.h>
#include <cuda_bf16.h>
#include <cstdint>

typedef unsigned long long ull;
typedef unsigned int uint;

#define BB 16
#define CC 64
#define NN 4096      // H*W
#define NP 1024      // pooled positions
#define L2E 1.4426950408889634f

// ---------------- scratch (device globals; no allocation) ----------------
__device__ __nv_bfloat16 g_theta_b[BB * NN * 8];   // [b][n][8]   bf16, pre-scaled by log2e
__device__ __nv_bfloat16 g_phi_b[BB * NP * 8];     // [b][p][8]   bf16
__device__ __nv_bfloat16 g_gT_b[BB * 32 * NP];     // [b][ch][p]  bf16 (transposed)

// ---------------- misc helpers ----------------
__device__ __forceinline__ ull pack2(float lo, float hi) {
    ull r; asm("mov.b64 %0, {%1,%2};" : "=l"(r) : "f"(lo), "f"(hi)); return r;
}
__device__ __forceinline__ void unpack2(ull v, float& lo, float& hi) {
    asm("mov.b64 {%0,%1}, %2;" : "=f"(lo), "=f"(hi) : "l"(v));
}
__device__ __forceinline__ void fma2(ull& d, ull a, ull b) {
    asm("fma.rn.f32x2 %0, %1, %2, %0;" : "+l"(d) : "l"(a), "l"(b));
}
__device__ __forceinline__ float ex2f(float x) {
    float r; asm("ex2.approx.f32 %0, %1;" : "=f"(r) : "f"(x)); return r;
}
// pack two f32 -> bf16x2 (first arg -> low half)
__device__ __forceinline__ uint bf2(float lo, float hi) {
    uint r; asm("cvt.rn.bf16x2.f32 %0, %1, %2;" : "=r"(r) : "f"(hi), "f"(lo)); return r;
}
__device__ __forceinline__ float shflx(float v, int m) {
    float r; asm("shfl.sync.bfly.b32 %0, %1, %2, 0x1F, 0xFFFFFFFF;" : "=f"(r) : "f"(v), "r"(m));
    return r;
}

// ---------------- mma.sync (base sm_80+ feature; OK on plain sm_100) -----
__device__ __forceinline__ void mma_16n8k8(float d[4], const uint a[2], uint b) {
    asm volatile(
        "mma.sync.aligned.m16n8k8.row.col.f32.bf16.bf16.f32 "
        "{%0,%1,%2,%3}, {%4,%5}, {%6}, {%0,%1,%2,%3};"
        : "+f"(d[0]), "+f"(d[1]), "+f"(d[2]), "+f"(d[3])
        : "r"(a[0]), "r"(a[1]), "r"(b));
}
__device__ __forceinline__ void mma_16n8k16(float d[4], const uint a[4], uint b0, uint b1) {
    asm volatile(
        "mma.sync.aligned.m16n8k16.row.col.f32.bf16.bf16.f32 "
        "{%0,%1,%2,%3}, {%4,%5,%6,%7}, {%8,%9}, {%0,%1,%2,%3};"
        : "+f"(d[0]), "+f"(d[1]), "+f"(d[2]), "+f"(d[3])
        : "r"(a[0]), "r"(a[1]), "r"(a[2]), "r"(a[3]), "r"(b0), "r"(b1));
}

// =========================================================================
// Kernel 1: 1x1 conv projections + 2x2 maxpool -> bf16 outputs. (unchanged)
// =========================================================================
__global__ void __launch_bounds__(256, 1)
proj_kernel(const float* __restrict__ x,
            const float* __restrict__ tw,
            const float* __restrict__ pw,
            const float* __restrict__ gw)
{
    __shared__ float ws[64 * 48];
    for (int i = threadIdx.x; i < 64 * 48; i += 256) {
        int k = i / 48, o = i % 48;
        float v;
        if (o < 8)        v = tw[o * 64 + k];
        else if (o < 16)  v = pw[(o - 8) * 64 + k];
        else              v = gw[(o - 16) * 64 + k];
        ws[i] = v;
    }
    __syncthreads();

    const int tid = threadIdx.x;
    const int dy  = tid & 1;
    int p  = blockIdx.x * 128 + (tid >> 1);
    int b  = p >> 10;
    int pp = p & 1023;
    int hp = pp >> 5, wp = pp & 31;

    const float* xb = x + (size_t)b * CC * NN;

    ull acc0[24], acc1[24];
#pragma unroll
    for (int c = 0; c < 24; c++) { acc0[c] = 0ull; acc1[c] = 0ull; }

    const float* xrow = xb + (2 * hp + dy) * 64 + 2 * wp;
#pragma unroll 4
    for (int k = 0; k < 64; k++) {
        float2 xv = *(const float2*)(xrow + (size_t)k * NN);
        ull a0 = pack2(xv.x, xv.x);
        ull a1 = pack2(xv.y, xv.y);
        const ull* w2 = (const ull*)(ws + k * 48);
#pragma unroll
        for (int c = 0; c < 24; c++) {
            ull w = w2[c];
            fma2(acc0[c], a0, w);
            fma2(acc1[c], a1, w);
        }
    }

    {
        int n0 = (2 * hp + dy) * 64 + 2 * wp;
        float u, v; uint4 q;
        unpack2(acc0[0], u, v); q.x = bf2(u * L2E, v * L2E);
        unpack2(acc0[1], u, v); q.y = bf2(u * L2E, v * L2E);
        unpack2(acc0[2], u, v); q.z = bf2(u * L2E, v * L2E);
        unpack2(acc0[3], u, v); q.w = bf2(u * L2E, v * L2E);
        *(uint4*)(g_theta_b + ((size_t)b * NN + n0) * 8) = q;
        unpack2(acc1[0], u, v); q.x = bf2(u * L2E, v * L2E);
        unpack2(acc1[1], u, v); q.y = bf2(u * L2E, v * L2E);
        unpack2(acc1[2], u, v); q.z = bf2(u * L2E, v * L2E);
        unpack2(acc1[3], u, v); q.w = bf2(u * L2E, v * L2E);
        *(uint4*)(g_theta_b + ((size_t)b * NN + n0 + 1) * 8) = q;
    }

    float best[40];
#pragma unroll
    for (int c = 4; c < 24; c++) {
        float u0, v0, u1, v1;
        unpack2(acc0[c], u0, v0);
        unpack2(acc1[c], u1, v1);
        best[2 * c - 8]     = fmaxf(u0, u1);
        best[2 * c - 8 + 1] = fmaxf(v0, v1);
    }
#pragma unroll
    for (int c = 0; c < 40; c++)
        best[c] = fmaxf(best[c], shflx(best[c], 1));

    if (dy == 0) {
        uint4 q;
        q.x = bf2(best[0], best[1]); q.y = bf2(best[2], best[3]);
        q.z = bf2(best[4], best[5]); q.w = bf2(best[6], best[7]);
        *(uint4*)(g_phi_b + ((size_t)b * NP + pp) * 8) = q;
    } else {
#pragma unroll
        for (int c = 0; c < 32; c++)
            g_gT_b[((size_t)b * 32 + c) * NP + pp] = __float2bfloat16(best[8 + c]);
    }
}

// =========================================================================
// Kernel 2: mma.sync flash attention + TENSOR-CORE o-projection + residual.
// 512 threads (16 warps), NQT=2, pipelined mainloop (R13). Epilogue:
// out(64ch x 512q) = ow(64x32) @ attn(32x512) via m16n8k16 bf16 mma,
// gamma/den scaling folded post-mma, coalesced float2 stores.
// =========================================================================
#define THREADS 512
#define NQT 2
#define SM_PHI   0                     // 16384
#define SM_GB    16384                 // 65536
#define SM_OWB   81920                 // 64 x 17 uints = 4352 (pad 4608)
#define SM_SC    86528                 // 512 f32 = 2048
#define SM_ATTB  88576                 // 512 x 17 uints = 34816
#define SMEM_BYTES (88576 + 34816)
#define ATTB_STRIDE 17
#define OWB_STRIDE 17

__global__ void __launch_bounds__(THREADS, 1)
attn_kernel(const float* __restrict__ x,
            const float* __restrict__ ow,
            const float* __restrict__ gamma_p,
            float* __restrict__ out)
{
    extern __shared__ char sm[];
    const int tid  = threadIdx.x;
    const int wid  = tid >> 5;
    const int lane = tid & 31;
    const int g    = lane >> 2;      // groupID
    const int tig  = lane & 3;       // thread-in-group
    const int b    = blockIdx.y;
    const int tile = blockIdx.x;

    // ---- stage phi [key][8ch] bf16 ----
    {
        const uint4* src = (const uint4*)(g_phi_b + (size_t)b * NP * 8);
        uint4* dst = (uint4*)(sm + SM_PHI);
        for (int i = tid; i < 1024; i += THREADS) dst[i] = src[i];
    }
    // ---- stage gB in b-frag order: [kc][nt][lane] = (b0|b1<<32) ----
    {
        const __nv_bfloat16* gT = g_gT_b + (size_t)b * 32 * NP;
        ull* dst = (ull*)(sm + SM_GB);
        for (int idx = tid; idx < 64 * 4 * 32; idx += THREADS) {
            int ln = idx & 31, nt = (idx >> 5) & 3, kc = idx >> 7;
            int ch = nt * 8 + (ln >> 2);
            const __nv_bfloat16* row = gT + (size_t)ch * NP + kc * 16 + 2 * (ln & 3);
            uint lo = *(const uint*)row;
            uint hi = *(const uint*)(row + 8);
            dst[idx] = (ull)lo | ((ull)hi << 32);
        }
    }
    // ---- stage ow as bf16 pairs: owB[ch][p] = bf16x2(ow[ch][2p], ow[ch][2p+1]) ----
    {
        uint* owB = (uint*)(sm + SM_OWB);
        for (int idx = tid; idx < 64 * 16; idx += THREADS) {
            int ch = idx >> 4, pr = idx & 15;
            float2 w = *(const float2*)(ow + ch * 32 + 2 * pr);
            owB[ch * OWB_STRIDE + pr] = bf2(w.x, w.y);
        }
    }
    __syncthreads();

    // ---- theta a-frags: NQT q-tiles of 16 rows ----
    const int wq = tile * 512 + wid * (16 * NQT);
    uint ta[NQT][2];
#pragma unroll
    for (int qt = 0; qt < NQT; qt++) {
        const __nv_bfloat16* t0 = g_theta_b + ((size_t)b * NN + wq + qt * 16 + g) * 8 + 2 * tig;
        ta[qt][0] = *(const uint*)t0;
        ta[qt][1] = *(const uint*)(t0 + 64);
    }

    float aoc[NQT][4][4];
#pragma unroll
    for (int qt = 0; qt < NQT; qt++)
#pragma unroll
        for (int nt = 0; nt < 4; nt++)
#pragma unroll
            for (int r = 0; r < 4; r++) aoc[qt][nt][r] = 0.f;
    float dn[NQT][2];
#pragma unroll
    for (int qt = 0; qt < NQT; qt++) { dn[qt][0] = 0.f; dn[qt][1] = 0.f; }

    const char* phiP = sm + SM_PHI + g * 16 + tig * 4;   // +256 B per kc
    const ull*  gP   = (const ull*)(sm + SM_GB) + lane;  // +128 ull per kc

    // prologue: load kc=0 operands (software pipeline)
    uint pb0 = *(const uint*)phiP;
    uint pb1 = *(const uint*)(phiP + 128);
    ull gv0 = gP[0], gv1 = gP[32], gv2 = gP[64], gv3 = gP[96];
    phiP += 256; gP += 128;

    for (int kc = 0; kc < 64; kc++) {
        uint npb0 = *(const uint*)phiP;
        uint npb1 = *(const uint*)(phiP + 128);
        ull ngv0 = gP[0], ngv1 = gP[32], ngv2 = gP[64], ngv3 = gP[96];
        phiP += 256; gP += 128;   // kc=63 prefetch stays in-bounds smem; discarded

        uint pa[NQT][4];
#pragma unroll
        for (int qt = 0; qt < NQT; qt++) {
            float s[4] = {0.f, 0.f, 0.f, 0.f};
            mma_16n8k8(s, ta[qt], pb0);
            float e0 = ex2f(s[0]), e1 = ex2f(s[1]);
            float e2 = ex2f(s[2]), e3 = ex2f(s[3]);
            dn[qt][0] += e0 + e1;
            dn[qt][1] += e2 + e3;
            pa[qt][0] = bf2(e0, e1);
            pa[qt][1] = bf2(e2, e3);
        }
#pragma unroll
        for (int qt = 0; qt < NQT; qt++) {
            float s[4] = {0.f, 0.f, 0.f, 0.f};
            mma_16n8k8(s, ta[qt], pb1);
            float e0 = ex2f(s[0]), e1 = ex2f(s[1]);
            float e2 = ex2f(s[2]), e3 = ex2f(s[3]);
            dn[qt][0] += e0 + e1;
            dn[qt][1] += e2 + e3;
            pa[qt][2] = bf2(e0, e1);
            pa[qt][3] = bf2(e2, e3);
        }
#pragma unroll
        for (int qt = 0; qt < NQT; qt++) {
            mma_16n8k16(aoc[qt][0], pa[qt], (uint)gv0, (uint)(gv0 >> 32));
            mma_16n8k16(aoc[qt][1], pa[qt], (uint)gv1, (uint)(gv1 >> 32));
            mma_16n8k16(aoc[qt][2], pa[qt], (uint)gv2, (uint)(gv2 >> 32));
            mma_16n8k16(aoc[qt][3], pa[qt], (uint)gv3, (uint)(gv3 >> 32));
        }
        pb0 = npb0; pb1 = npb1;
        gv0 = ngv0; gv1 = ngv1; gv2 = ngv2; gv3 = ngv3;
    }

    // ---- den reduce + store sc = gamma/den; pack attn -> bf16x2 smem ----
    const float gamma = *gamma_p;
    float* scS  = (float*)(sm + SM_SC);
    uint*  attB = (uint*)(sm + SM_ATTB);
    const int wqp = wid * (16 * NQT);
#pragma unroll
    for (int qt = 0; qt < NQT; qt++) {
        float d0 = dn[qt][0]; d0 += shflx(d0, 1); d0 += shflx(d0, 2);
        float d1 = dn[qt][1]; d1 += shflx(d1, 1); d1 += shflx(d1, 2);
        if (tig == 0) {
            scS[wqp + qt * 16 + g]     = gamma / d0;
            scS[wqp + qt * 16 + g + 8] = gamma / d1;
        }
        const int q0 = wqp + qt * 16 + g;
#pragma unroll
        for (int nt = 0; nt < 4; nt++) {
            attB[(size_t)q0 * ATTB_STRIDE + nt * 4 + tig]       = bf2(aoc[qt][nt][0], aoc[qt][nt][1]);
            attB[(size_t)(q0 + 8) * ATTB_STRIDE + nt * 4 + tig] = bf2(aoc[qt][nt][2], aoc[qt][nt][3]);
        }
    }
    __syncthreads();

    // ---- tensor-core epilogue: out = sc[q] * (ow @ attn) + x ----
    // warp w covers queries [32w, 32w+32) via 4 n-tiles; all 4 m-tiles (64 ch).
    const uint* owB = (const uint*)(sm + SM_OWB);
    uint af[4][2][4];
#pragma unroll
    for (int mt = 0; mt < 4; mt++)
#pragma unroll
        for (int ks = 0; ks < 2; ks++) {
            const uint* wr = owB + (mt * 16 + g) * OWB_STRIDE + tig + 8 * ks;
            af[mt][ks][0] = wr[0];
            af[mt][ks][1] = wr[8 * OWB_STRIDE];
            af[mt][ks][2] = wr[4];
            af[mt][ks][3] = wr[8 * OWB_STRIDE + 4];
        }

    const float* xb2 = x + (size_t)b * CC * NN;
    float*       ob2 = out + (size_t)b * CC * NN;
#pragma unroll
    for (int nt2 = 0; nt2 < 4; nt2++) {
        const int qb = wid * 32 + nt2 * 8;           // local query base
        const uint* br = attB + (size_t)(qb + g) * ATTB_STRIDE + tig;
        uint b00 = br[0], b01 = br[4], b10 = br[8], b11 = br[12];
        const float s0 = scS[qb + 2 * tig];
        const float s1 = scS[qb + 2 * tig + 1];
        const int qg = tile * 512 + qb + 2 * tig;    // global query for this lane
#pragma unroll
        for (int mt = 0; mt < 4; mt++) {
            float c[4] = {0.f, 0.f, 0.f, 0.f};
            mma_16n8k16(c, af[mt][0], b00, b01);
            mma_16n8k16(c, af[mt][1], b10, b11);
            const int ch0 = mt * 16 + g;
            float2 x0 = *(const float2*)(xb2 + (size_t)ch0 * NN + qg);
            float2 x1 = *(const float2*)(xb2 + (size_t)(ch0 + 8) * NN + qg);
            *(float2*)(ob2 + (size_t)ch0 * NN + qg) =
                make_float2(fmaf(c[0], s0, x0.x), fmaf(c[1], s1, x0.y));
            *(float2*)(ob2 + (size_t)(ch0 + 8) * NN + qg) =
                make_float2(fmaf(c[2], s0, x1.x), fmaf(c[3], s1, x1.y));
        }
    }
}

// =========================================================================
extern "C" void kernel_launch(void* const* d_in, const int* in_sizes, int n_in,
                              void* d_out, int out_size)
{
    const float* x     = (const float*)d_in[0];
    const float* tw    = (const float*)d_in[1];
    const float* pw    = (const float*)d_in[2];
    const float* gw    = (const float*)d_in[3];
    const float* ow    = (const float*)d_in[4];
    const float* gamma = (const float*)d_in[5];
    float* out = (float*)d_out;

    cudaFuncSetAttribute(attn_kernel,
                         cudaFuncAttributeMaxDynamicSharedMemorySize, SMEM_BYTES);

    proj_kernel<<<BB * NP / 128, 256>>>(x, tw, pw, gw);
    attn_kernel<<<dim3(8, BB), THREADS, SMEM_BYTES>>>(x, ow, gamma, out);
}

// round 16
// speedup vs baseline: 1.2814x; 1.0241x over previous
#include <cuda_runtime.h>
#include <cuda_bf16.h>
#include <cstdint>

typedef unsigned long long ull;
typedef unsigned int uint;

#define BB 16
#define CC 64
#define NN 4096      // H*W
#define NP 1024      // pooled positions
#define L2E 1.4426950408889634f

// ---------------- scratch (device globals; no allocation) ----------------
__device__ __nv_bfloat16 g_theta_b[BB * NN * 8];   // [b][n][8]   bf16, pre-scaled by log2e
__device__ __nv_bfloat16 g_phi_b[BB * NP * 8];     // [b][p][8]   bf16
__device__ __nv_bfloat16 g_gT_b[BB * 32 * NP];     // [b][ch][p]  bf16 (transposed)

// ---------------- misc helpers ----------------
__device__ __forceinline__ ull pack2(float lo, float hi) {
    ull r; asm("mov.b64 %0, {%1,%2};" : "=l"(r) : "f"(lo), "f"(hi)); return r;
}
__device__ __forceinline__ void unpack2(ull v, float& lo, float& hi) {
    asm("mov.b64 {%0,%1}, %2;" : "=f"(lo), "=f"(hi) : "l"(v));
}
__device__ __forceinline__ void fma2(ull& d, ull a, ull b) {
    asm("fma.rn.f32x2 %0, %1, %2, %0;" : "+l"(d) : "l"(a), "l"(b));
}
__device__ __forceinline__ float ex2f(float x) {
    float r; asm("ex2.approx.f32 %0, %1;" : "=f"(r) : "f"(x)); return r;
}
// pack two f32 -> bf16x2 (first arg -> low half)
__device__ __forceinline__ uint bf2(float lo, float hi) {
    uint r; asm("cvt.rn.bf16x2.f32 %0, %1, %2;" : "=r"(r) : "f"(hi), "f"(lo)); return r;
}
__device__ __forceinline__ float shflx(float v, int m) {
    float r; asm("shfl.sync.bfly.b32 %0, %1, %2, 0x1F, 0xFFFFFFFF;" : "=f"(r) : "f"(v), "r"(m));
    return r;
}

// ---------------- mma.sync (base sm_80+ feature; OK on plain sm_100) -----
__device__ __forceinline__ void mma_16n8k8(float d[4], const uint a[2], uint b) {
    asm volatile(
        "mma.sync.aligned.m16n8k8.row.col.f32.bf16.bf16.f32 "
        "{%0,%1,%2,%3}, {%4,%5}, {%6}, {%0,%1,%2,%3};"
        : "+f"(d[0]), "+f"(d[1]), "+f"(d[2]), "+f"(d[3])
        : "r"(a[0]), "r"(a[1]), "r"(b));
}
__device__ __forceinline__ void mma_16n8k16(float d[4], const uint a[4], uint b0, uint b1) {
    asm volatile(
        "mma.sync.aligned.m16n8k16.row.col.f32.bf16.bf16.f32 "
        "{%0,%1,%2,%3}, {%4,%5,%6,%7}, {%8,%9}, {%0,%1,%2,%3};"
        : "+f"(d[0]), "+f"(d[1]), "+f"(d[2]), "+f"(d[3])
        : "r"(a[0]), "r"(a[1]), "r"(a[2]), "r"(a[3]), "r"(b0), "r"(b1));
}

// =========================================================================
// Kernel 1: 1x1 conv projections + 2x2 maxpool -> bf16 outputs. (unchanged,
// at its fp32-FMA floor ~7us)
// =========================================================================
__global__ void __launch_bounds__(256, 1)
proj_kernel(const float* __restrict__ x,
            const float* __restrict__ tw,
            const float* __restrict__ pw,
            const float* __restrict__ gw)
{
    __shared__ float ws[64 * 48];
    for (int i = threadIdx.x; i < 64 * 48; i += 256) {
        int k = i / 48, o = i % 48;
        float v;
        if (o < 8)        v = tw[o * 64 + k];
        else if (o < 16)  v = pw[(o - 8) * 64 + k];
        else              v = gw[(o - 16) * 64 + k];
        ws[i] = v;
    }
    __syncthreads();

    const int tid = threadIdx.x;
    const int dy  = tid & 1;
    int p  = blockIdx.x * 128 + (tid >> 1);
    int b  = p >> 10;
    int pp = p & 1023;
    int hp = pp >> 5, wp = pp & 31;

    const float* xb = x + (size_t)b * CC * NN;

    ull acc0[24], acc1[24];
#pragma unroll
    for (int c = 0; c < 24; c++) { acc0[c] = 0ull; acc1[c] = 0ull; }

    const float* xrow = xb + (2 * hp + dy) * 64 + 2 * wp;
#pragma unroll 4
    for (int k = 0; k < 64; k++) {
        float2 xv = *(const float2*)(xrow + (size_t)k * NN);
        ull a0 = pack2(xv.x, xv.x);
        ull a1 = pack2(xv.y, xv.y);
        const ull* w2 = (const ull*)(ws + k * 48);
#pragma unroll
        for (int c = 0; c < 24; c++) {
            ull w = w2[c];
            fma2(acc0[c], a0, w);
            fma2(acc1[c], a1, w);
        }
    }

    {
        int n0 = (2 * hp + dy) * 64 + 2 * wp;
        float u, v; uint4 q;
        unpack2(acc0[0], u, v); q.x = bf2(u * L2E, v * L2E);
        unpack2(acc0[1], u, v); q.y = bf2(u * L2E, v * L2E);
        unpack2(acc0[2], u, v); q.z = bf2(u * L2E, v * L2E);
        unpack2(acc0[3], u, v); q.w = bf2(u * L2E, v * L2E);
        *(uint4*)(g_theta_b + ((size_t)b * NN + n0) * 8) = q;
        unpack2(acc1[0], u, v); q.x = bf2(u * L2E, v * L2E);
        unpack2(acc1[1], u, v); q.y = bf2(u * L2E, v * L2E);
        unpack2(acc1[2], u, v); q.z = bf2(u * L2E, v * L2E);
        unpack2(acc1[3], u, v); q.w = bf2(u * L2E, v * L2E);
        *(uint4*)(g_theta_b + ((size_t)b * NN + n0 + 1) * 8) = q;
    }

    float best[40];
#pragma unroll
    for (int c = 4; c < 24; c++) {
        float u0, v0, u1, v1;
        unpack2(acc0[c], u0, v0);
        unpack2(acc1[c], u1, v1);
        best[2 * c - 8]     = fmaxf(u0, u1);
        best[2 * c - 8 + 1] = fmaxf(v0, v1);
    }
#pragma unroll
    for (int c = 0; c < 40; c++)
        best[c] = fmaxf(best[c], shflx(best[c], 1));

    if (dy == 0) {
        uint4 q;
        q.x = bf2(best[0], best[1]); q.y = bf2(best[2], best[3]);
        q.z = bf2(best[4], best[5]); q.w = bf2(best[6], best[7]);
        *(uint4*)(g_phi_b + ((size_t)b * NP + pp) * 8) = q;
    } else {
#pragma unroll
        for (int c = 0; c < 32; c++)
            g_gT_b[((size_t)b * 32 + c) * NP + pp] = __float2bfloat16(best[8 + c]);
    }
}

// =========================================================================
// Kernel 2: mma.sync flash attention + tensor-core o-projection + residual.
// 1024 threads (32 warps = 8/SMSP). Warp owns 16 queries (one m16 tile).
// ~50 regs/thread -> full residency; tensor epilogue keeps L1 traffic low.
// =========================================================================
#define THREADS 1024
#define SM_PHI   0                     // 16384
#define SM_GB    16384                 // 65536
#define SM_OWB   81920                 // 64 x 17 uints (pad 4608)
#define SM_SC    86528                 // 512 f32 = 2048
#define SM_ATTB  88576                 // 512 x 17 uints = 34816
#define SMEM_BYTES (88576 + 34816)
#define ATTB_STRIDE 17
#define OWB_STRIDE 17

__global__ void __launch_bounds__(THREADS, 1)
attn_kernel(const float* __restrict__ x,
            const float* __restrict__ ow,
            const float* __restrict__ gamma_p,
            float* __restrict__ out)
{
    extern __shared__ char sm[];
    const int tid  = threadIdx.x;
    const int wid  = tid >> 5;
    const int lane = tid & 31;
    const int g    = lane >> 2;      // groupID
    const int tig  = lane & 3;       // thread-in-group
    const int b    = blockIdx.y;
    const int tile = blockIdx.x;

    // ---- stage phi [key][8ch] bf16 ----
    {
        const uint4* src = (const uint4*)(g_phi_b + (size_t)b * NP * 8);
        uint4* dst = (uint4*)(sm + SM_PHI);
        for (int i = tid; i < 1024; i += THREADS) dst[i] = src[i];
    }
    // ---- stage gB in b-frag order: [kc][nt][lane] = (b0|b1<<32) ----
    {
        const __nv_bfloat16* gT = g_gT_b + (size_t)b * 32 * NP;
        ull* dst = (ull*)(sm + SM_GB);
        for (int idx = tid; idx < 64 * 4 * 32; idx += THREADS) {
            int ln = idx & 31, nt = (idx >> 5) & 3, kc = idx >> 7;
            int ch = nt * 8 + (ln >> 2);
            const __nv_bfloat16* row = gT + (size_t)ch * NP + kc * 16 + 2 * (ln & 3);
            uint lo = *(const uint*)row;
            uint hi = *(const uint*)(row + 8);
            dst[idx] = (ull)lo | ((ull)hi << 32);
        }
    }
    // ---- stage ow as bf16 pairs: owB[ch][p] = bf16x2(ow[ch][2p], ow[ch][2p+1]) ----
    {
        uint* owB = (uint*)(sm + SM_OWB);
        for (int idx = tid; idx < 64 * 16; idx += THREADS) {
            int ch = idx >> 4, pr = idx & 15;
            float2 w = *(const float2*)(ow + ch * 32 + 2 * pr);
            owB[ch * OWB_STRIDE + pr] = bf2(w.x, w.y);
        }
    }
    __syncthreads();

    // ---- theta a-frag: warp's single 16-row q-tile ----
    const int wq = tile * 512 + wid * 16;
    uint ta[2];
    {
        const __nv_bfloat16* t0 = g_theta_b + ((size_t)b * NN + wq + g) * 8 + 2 * tig;
        ta[0] = *(const uint*)t0;
        ta[1] = *(const uint*)(t0 + 64);
    }

    float aoc[4][4];
#pragma unroll
    for (int nt = 0; nt < 4; nt++)
#pragma unroll
        for (int r = 0; r < 4; r++) aoc[nt][r] = 0.f;
    float dn0 = 0.f, dn1 = 0.f;

    const char* phiP = sm + SM_PHI + g * 16 + tig * 4;   // +256 B per kc
    const ull*  gP   = (const ull*)(sm + SM_GB) + lane;  // +128 ull per kc

#pragma unroll 2
    for (int kc = 0; kc < 64; kc++) {
        uint pb0 = *(const uint*)phiP;
        uint pb1 = *(const uint*)(phiP + 128);
        ull gv0 = gP[0], gv1 = gP[32], gv2 = gP[64], gv3 = gP[96];
        phiP += 256; gP += 128;

        uint pa[4];
        {
            float s[4] = {0.f, 0.f, 0.f, 0.f};
            mma_16n8k8(s, ta, pb0);
            float e0 = ex2f(s[0]), e1 = ex2f(s[1]);
            float e2 = ex2f(s[2]), e3 = ex2f(s[3]);
            dn0 += e0 + e1;
            dn1 += e2 + e3;
            pa[0] = bf2(e0, e1);
            pa[1] = bf2(e2, e3);
        }
        {
            float s[4] = {0.f, 0.f, 0.f, 0.f};
            mma_16n8k8(s, ta, pb1);
            float e0 = ex2f(s[0]), e1 = ex2f(s[1]);
            float e2 = ex2f(s[2]), e3 = ex2f(s[3]);
            dn0 += e0 + e1;
            dn1 += e2 + e3;
            pa[2] = bf2(e0, e1);
            pa[3] = bf2(e2, e3);
        }
        mma_16n8k16(aoc[0], pa, (uint)gv0, (uint)(gv0 >> 32));
        mma_16n8k16(aoc[1], pa, (uint)gv1, (uint)(gv1 >> 32));
        mma_16n8k16(aoc[2], pa, (uint)gv2, (uint)(gv2 >> 32));
        mma_16n8k16(aoc[3], pa, (uint)gv3, (uint)(gv3 >> 32));
    }

    // ---- den reduce + store sc = gamma/den; pack attn -> bf16x2 smem ----
    const float gamma = *gamma_p;
    float* scS  = (float*)(sm + SM_SC);
    uint*  attB = (uint*)(sm + SM_ATTB);
    const int wqp = wid * 16;
    {
        float d0 = dn0; d0 += shflx(d0, 1); d0 += shflx(d0, 2);
        float d1 = dn1; d1 += shflx(d1, 1); d1 += shflx(d1, 2);
        if (tig == 0) {
            scS[wqp + g]     = gamma / d0;
            scS[wqp + g + 8] = gamma / d1;
        }
        const int q0 = wqp + g;
#pragma unroll
        for (int nt = 0; nt < 4; nt++) {
            attB[(size_t)q0 * ATTB_STRIDE + nt * 4 + tig]       = bf2(aoc[nt][0], aoc[nt][1]);
            attB[(size_t)(q0 + 8) * ATTB_STRIDE + nt * 4 + tig] = bf2(aoc[nt][2], aoc[nt][3]);
        }
    }
    __syncthreads();

    // ---- tensor-core epilogue: out = sc[q] * (ow @ attn) + x ----
    // warp w covers queries [16w, 16w+16) via 2 n-tiles; all 4 m-tiles (64 ch).
    const uint* owB = (const uint*)(sm + SM_OWB);
    uint af[4][2][4];
#pragma unroll
    for (int mt = 0; mt < 4; mt++)
#pragma unroll
        for (int ks = 0; ks < 2; ks++) {
            const uint* wr = owB + (mt * 16 + g) * OWB_STRIDE + tig + 8 * ks;
            af[mt][ks][0] = wr[0];
            af[mt][ks][1] = wr[8 * OWB_STRIDE];
            af[mt][ks][2] = wr[4];
            af[mt][ks][3] = wr[8 * OWB_STRIDE + 4];
        }

    const float* xb2 = x + (size_t)b * CC * NN;
    float*       ob2 = out + (size_t)b * CC * NN;
#pragma unroll
    for (int nt2 = 0; nt2 < 2; nt2++) {
        const int qb = wid * 16 + nt2 * 8;           // local query base
        const uint* br = attB + (size_t)(qb + g) * ATTB_STRIDE + tig;
        uint b00 = br[0], b01 = br[4], b10 = br[8], b11 = br[12];
        const float s0 = scS[qb + 2 * tig];
        const float s1 = scS[qb + 2 * tig + 1];
        const int qg = tile * 512 + qb + 2 * tig;    // global query for this lane
#pragma unroll
        for (int mt = 0; mt < 4; mt++) {
            float c[4] = {0.f, 0.f, 0.f, 0.f};
            mma_16n8k16(c, af[mt][0], b00, b01);
            mma_16n8k16(c, af[mt][1], b10, b11);
            const int ch0 = mt * 16 + g;
            float2 x0 = *(const float2*)(xb2 + (size_t)ch0 * NN + qg);
            float2 x1 = *(const float2*)(xb2 + (size_t)(ch0 + 8) * NN + qg);
            *(float2*)(ob2 + (size_t)ch0 * NN + qg) =
                make_float2(fmaf(c[0], s0, x0.x), fmaf(c[1], s1, x0.y));
            *(float2*)(ob2 + (size_t)(ch0 + 8) * NN + qg) =
                make_float2(fmaf(c[2], s0, x1.x), fmaf(c[3], s1, x1.y));
        }
    }
}

// =========================================================================
extern "C" void kernel_launch(void* const* d_in, const int* in_sizes, int n_in,
                              void* d_out, int out_size)
{
    const float* x     = (const float*)d_in[0];
    const float* tw    = (const float*)d_in[1];
    const float* pw    = (const float*)d_in[2];
    const float* gw    = (const float*)d_in[3];
    const float* ow    = (const float*)d_in[4];
    const float* gamma = (const float*)d_in[5];
    float* out = (float*)d_out;

    cudaFuncSetAttribute(attn_kernel,
                         cudaFuncAttributeMaxDynamicSharedMemorySize, SMEM_BYTES);

    proj_kernel<<<BB * NP / 128, 256>>>(x, tw, pw, gw);
    attn_kernel<<<dim3(8, BB), THREADS, SMEM_BYTES>>>(x, ow, gamma, out);
}

// round 17
// speedup vs baseline: 1.3079x; 1.0207x over previous
#include <cuda_runtime.h>
#include <cuda_bf16.h>
#include <cuda_fp16.h>
#include <cstdint>

typedef unsigned long long ull;
typedef unsigned int uint;

#define BB 16
#define CC 64
#define NN 4096      // H*W
#define NP 1024      // pooled positions
#define L2E 1.4426950408889634f

// ---------------- scratch (device globals; no allocation) ----------------
__device__ __nv_bfloat16 g_theta_b[BB * NN * 8];   // [b][n][8]   bf16, pre-scaled by log2e
__device__ __nv_bfloat16 g_phi_b[BB * NP * 8];     // [b][p][8]   bf16
__device__ __half        g_gT_h[BB * 32 * NP];     // [b][ch][p]  fp16 (transposed)

// ---------------- misc helpers ----------------
__device__ __forceinline__ ull pack2(float lo, float hi) {
    ull r; asm("mov.b64 %0, {%1,%2};" : "=l"(r) : "f"(lo), "f"(hi)); return r;
}
__device__ __forceinline__ void unpack2(ull v, float& lo, float& hi) {
    asm("mov.b64 {%0,%1}, %2;" : "=f"(lo), "=f"(hi) : "l"(v));
}
__device__ __forceinline__ void fma2(ull& d, ull a, ull b) {
    asm("fma.rn.f32x2 %0, %1, %2, %0;" : "+l"(d) : "l"(a), "l"(b));
}
// pack two f32 -> bf16x2 (first arg -> low half)
__device__ __forceinline__ uint bf2(float lo, float hi) {
    uint r; asm("cvt.rn.bf16x2.f32 %0, %1, %2;" : "=r"(r) : "f"(hi), "f"(lo)); return r;
}
// pack two f32 -> f16x2 (first arg -> low half)
__device__ __forceinline__ uint h2pk(float lo, float hi) {
    uint r; asm("cvt.rn.f16x2.f32 %0, %1, %2;" : "=r"(r) : "f"(hi), "f"(lo)); return r;
}
// vector exp2 on two fp16 values
__device__ __forceinline__ uint ex2h2(uint x) {
    uint r; asm("ex2.approx.f16x2 %0, %1;" : "=r"(r) : "r"(x)); return r;
}
__device__ __forceinline__ uint hadd2(uint a, uint b) {
    uint r; asm("add.rn.f16x2 %0, %1, %2;" : "=r"(r) : "r"(a), "r"(b)); return r;
}
__device__ __forceinline__ float shflx(float v, int m) {
    float r; asm("shfl.sync.bfly.b32 %0, %1, %2, 0x1F, 0xFFFFFFFF;" : "=f"(r) : "f"(v), "r"(m));
    return r;
}

// ---------------- mma.sync (base sm_80+ feature; OK on plain sm_100) -----
__device__ __forceinline__ void mma_16n8k8(float d[4], const uint a[2], uint b) {
    asm volatile(
        "mma.sync.aligned.m16n8k8.row.col.f32.bf16.bf16.f32 "
        "{%0,%1,%2,%3}, {%4,%5}, {%6}, {%0,%1,%2,%3};"
        : "+f"(d[0]), "+f"(d[1]), "+f"(d[2]), "+f"(d[3])
        : "r"(a[0]), "r"(a[1]), "r"(b));
}
__device__ __forceinline__ void mma_16n8k16(float d[4], const uint a[4], uint b0, uint b1) {
    asm volatile(
        "mma.sync.aligned.m16n8k16.row.col.f32.bf16.bf16.f32 "
        "{%0,%1,%2,%3}, {%4,%5,%6,%7}, {%8,%9}, {%0,%1,%2,%3};"
        : "+f"(d[0]), "+f"(d[1]), "+f"(d[2]), "+f"(d[3])
        : "r"(a[0]), "r"(a[1]), "r"(a[2]), "r"(a[3]), "r"(b0), "r"(b1));
}
// f16-input variant (P and g are fp16)
__device__ __forceinline__ void mma_16n8k16h(float d[4], const uint a[4], uint b0, uint b1) {
    asm volatile(
        "mma.sync.aligned.m16n8k16.row.col.f32.f16.f16.f32 "
        "{%0,%1,%2,%3}, {%4,%5,%6,%7}, {%8,%9}, {%0,%1,%2,%3};"
        : "+f"(d[0]), "+f"(d[1]), "+f"(d[2]), "+f"(d[3])
        : "r"(a[0]), "r"(a[1]), "r"(a[2]), "r"(a[3]), "r"(b0), "r"(b1));
}

// =========================================================================
// Kernel 1: 1x1 conv projections + 2x2 maxpool -> bf16/fp16 outputs.
// =========================================================================
__global__ void __launch_bounds__(256, 1)
proj_kernel(const float* __restrict__ x,
            const float* __restrict__ tw,
            const float* __restrict__ pw,
            const float* __restrict__ gw)
{
    __shared__ float ws[64 * 48];
    for (int i = threadIdx.x; i < 64 * 48; i += 256) {
        int k = i / 48, o = i % 48;
        float v;
        if (o < 8)        v = tw[o * 64 + k];
        else if (o < 16)  v = pw[(o - 8) * 64 + k];
        else              v = gw[(o - 16) * 64 + k];
        ws[i] = v;
    }
    __syncthreads();

    const int tid = threadIdx.x;
    const int dy  = tid & 1;
    int p  = blockIdx.x * 128 + (tid >> 1);
    int b  = p >> 10;
    int pp = p & 1023;
    int hp = pp >> 5, wp = pp & 31;

    const float* xb = x + (size_t)b * CC * NN;

    ull acc0[24], acc1[24];
#pragma unroll
    for (int c = 0; c < 24; c++) { acc0[c] = 0ull; acc1[c] = 0ull; }

    const float* xrow = xb + (2 * hp + dy) * 64 + 2 * wp;
#pragma unroll 4
    for (int k = 0; k < 64; k++) {
        float2 xv = *(const float2*)(xrow + (size_t)k * NN);
        ull a0 = pack2(xv.x, xv.x);
        ull a1 = pack2(xv.y, xv.y);
        const ull* w2 = (const ull*)(ws + k * 48);
#pragma unroll
        for (int c = 0; c < 24; c++) {
            ull w = w2[c];
            fma2(acc0[c], a0, w);
            fma2(acc1[c], a1, w);
        }
    }

    {
        int n0 = (2 * hp + dy) * 64 + 2 * wp;
        float u, v; uint4 q;
        unpack2(acc0[0], u, v); q.x = bf2(u * L2E, v * L2E);
        unpack2(acc0[1], u, v); q.y = bf2(u * L2E, v * L2E);
        unpack2(acc0[2], u, v); q.z = bf2(u * L2E, v * L2E);
        unpack2(acc0[3], u, v); q.w = bf2(u * L2E, v * L2E);
        *(uint4*)(g_theta_b + ((size_t)b * NN + n0) * 8) = q;
        unpack2(acc1[0], u, v); q.x = bf2(u * L2E, v * L2E);
        unpack2(acc1[1], u, v); q.y = bf2(u * L2E, v * L2E);
        unpack2(acc1[2], u, v); q.z = bf2(u * L2E, v * L2E);
        unpack2(acc1[3], u, v); q.w = bf2(u * L2E, v * L2E);
        *(uint4*)(g_theta_b + ((size_t)b * NN + n0 + 1) * 8) = q;
    }

    float best[40];
#pragma unroll
    for (int c = 4; c < 24; c++) {
        float u0, v0, u1, v1;
        unpack2(acc0[c], u0, v0);
        unpack2(acc1[c], u1, v1);
        best[2 * c - 8]     = fmaxf(u0, u1);
        best[2 * c - 8 + 1] = fmaxf(v0, v1);
    }
#pragma unroll
    for (int c = 0; c < 40; c++)
        best[c] = fmaxf(best[c], shflx(best[c], 1));

    if (dy == 0) {
        uint4 q;
        q.x = bf2(best[0], best[1]); q.y = bf2(best[2], best[3]);
        q.z = bf2(best[4], best[5]); q.w = bf2(best[6], best[7]);
        *(uint4*)(g_phi_b + ((size_t)b * NP + pp) * 8) = q;
    } else {
#pragma unroll
        for (int c = 0; c < 32; c++)
            g_gT_h[((size_t)b * 32 + c) * NP + pp] = __float2half(best[8 + c]);
    }
}

// =========================================================================
// Kernel 2: mma.sync flash attention + tensor-core o-projection + residual.
// 1024 threads (32 warps = 8/SMSP). Warp owns 16 queries (one m16 tile).
// Softmax via ex2.approx.f16x2 (2 exps/MUFU op); P + g in fp16 for GEMM2.
// =========================================================================
#define THREADS 1024
#define SM_PHI   0                     // 16384
#define SM_GB    16384                 // 65536
#define SM_OWB   81920                 // 64 x 17 uints (pad 4608)
#define SM_SC    86528                 // 512 f32 = 2048
#define SM_ATTB  88576                 // 512 x 17 uints = 34816
#define SMEM_BYTES (88576 + 34816)
#define ATTB_STRIDE 17
#define OWB_STRIDE 17

__global__ void __launch_bounds__(THREADS, 1)
attn_kernel(const float* __restrict__ x,
            const float* __restrict__ ow,
            const float* __restrict__ gamma_p,
            float* __restrict__ out)
{
    extern __shared__ char sm[];
    const int tid  = threadIdx.x;
    const int wid  = tid >> 5;
    const int lane = tid & 31;
    const int g    = lane >> 2;      // groupID
    const int tig  = lane & 3;       // thread-in-group
    const int b    = blockIdx.y;
    const int tile = blockIdx.x;

    // ---- stage phi [key][8ch] bf16 ----
    {
        const uint4* src = (const uint4*)(g_phi_b + (size_t)b * NP * 8);
        uint4* dst = (uint4*)(sm + SM_PHI);
        for (int i = tid; i < 1024; i += THREADS) dst[i] = src[i];
    }
    // ---- stage gB (fp16) in b-frag order: [kc][nt][lane] = (b0|b1<<32) ----
    {
        const __half* gT = g_gT_h + (size_t)b * 32 * NP;
        ull* dst = (ull*)(sm + SM_GB);
        for (int idx = tid; idx < 64 * 4 * 32; idx += THREADS) {
            int ln = idx & 31, nt = (idx >> 5) & 3, kc = idx >> 7;
            int ch = nt * 8 + (ln >> 2);
            const __half* row = gT + (size_t)ch * NP + kc * 16 + 2 * (ln & 3);
            uint lo = *(const uint*)row;
            uint hi = *(const uint*)(row + 8);
            dst[idx] = (ull)lo | ((ull)hi << 32);
        }
    }
    // ---- stage ow as bf16 pairs ----
    {
        uint* owB = (uint*)(sm + SM_OWB);
        for (int idx = tid; idx < 64 * 16; idx += THREADS) {
            int ch = idx >> 4, pr = idx & 15;
            float2 w = *(const float2*)(ow + ch * 32 + 2 * pr);
            owB[ch * OWB_STRIDE + pr] = bf2(w.x, w.y);
        }
    }
    __syncthreads();

    // ---- theta a-frag: warp's single 16-row q-tile ----
    const int wq = tile * 512 + wid * 16;
    uint ta[2];
    {
        const __nv_bfloat16* t0 = g_theta_b + ((size_t)b * NN + wq + g) * 8 + 2 * tig;
        ta[0] = *(const uint*)t0;
        ta[1] = *(const uint*)(t0 + 64);
    }

    float aoc[4][4];
#pragma unroll
    for (int nt = 0; nt < 4; nt++)
#pragma unroll
        for (int r = 0; r < 4; r++) aoc[nt][r] = 0.f;
    uint dnh0 = 0u, dnh1 = 0u;   // half2 accumulators (q=g / q=g+8)

    const char* phiP = sm + SM_PHI + g * 16 + tig * 4;   // +256 B per kc
    const ull*  gP   = (const ull*)(sm + SM_GB) + lane;  // +128 ull per kc

#pragma unroll 2
    for (int kc = 0; kc < 64; kc++) {
        uint pb0 = *(const uint*)phiP;
        uint pb1 = *(const uint*)(phiP + 128);
        ull gv0 = gP[0], gv1 = gP[32], gv2 = gP[64], gv3 = gP[96];
        phiP += 256; gP += 128;

        uint pa[4];
        {
            float s[4] = {0.f, 0.f, 0.f, 0.f};
            mma_16n8k8(s, ta, pb0);
            pa[0] = ex2h2(h2pk(s[0], s[1]));   // q=g,   keys 2tig..+1 (fp16x2)
            pa[1] = ex2h2(h2pk(s[2], s[3]));   // q=g+8
            dnh0 = hadd2(dnh0, pa[0]);
            dnh1 = hadd2(dnh1, pa[1]);
        }
        {
            float s[4] = {0.f, 0.f, 0.f, 0.f};
            mma_16n8k8(s, ta, pb1);
            pa[2] = ex2h2(h2pk(s[0], s[1]));
            pa[3] = ex2h2(h2pk(s[2], s[3]));
            dnh0 = hadd2(dnh0, pa[2]);
            dnh1 = hadd2(dnh1, pa[3]);
        }
        mma_16n8k16h(aoc[0], pa, (uint)gv0, (uint)(gv0 >> 32));
        mma_16n8k16h(aoc[1], pa, (uint)gv1, (uint)(gv1 >> 32));
        mma_16n8k16h(aoc[2], pa, (uint)gv2, (uint)(gv2 >> 32));
        mma_16n8k16h(aoc[3], pa, (uint)gv3, (uint)(gv3 >> 32));
    }

    // ---- den reduce + store sc = gamma/den; pack attn -> bf16x2 smem ----
    const float gamma = *gamma_p;
    float* scS  = (float*)(sm + SM_SC);
    uint*  attB = (uint*)(sm + SM_ATTB);
    const int wqp = wid * 16;
    {
        __half2 h0 = *(__half2*)&dnh0;
        __half2 h1 = *(__half2*)&dnh1;
        float dn0 = __low2float(h0) + __high2float(h0);
        float dn1 = __low2float(h1) + __high2float(h1);
        float d0 = dn0; d0 += shflx(d0, 1); d0 += shflx(d0, 2);
        float d1 = dn1; d1 += shflx(d1, 1); d1 += shflx(d1, 2);
        if (tig == 0) {
            scS[wqp + g]     = gamma / d0;
            scS[wqp + g + 8] = gamma / d1;
        }
        const int q0 = wqp + g;
#pragma unroll
        for (int nt = 0; nt < 4; nt++) {
            attB[(size_t)q0 * ATTB_STRIDE + nt * 4 + tig]       = bf2(aoc[nt][0], aoc[nt][1]);
            attB[(size_t)(q0 + 8) * ATTB_STRIDE + nt * 4 + tig] = bf2(aoc[nt][2], aoc[nt][3]);
        }
    }
    __syncthreads();

    // ---- tensor-core epilogue: out = sc[q] * (ow @ attn) + x ----
    const uint* owB = (const uint*)(sm + SM_OWB);
    uint af[4][2][4];
#pragma unroll
    for (int mt = 0; mt < 4; mt++)
#pragma unroll
        for (int ks = 0; ks < 2; ks++) {
            const uint* wr = owB + (mt * 16 + g) * OWB_STRIDE + tig + 8 * ks;
            af[mt][ks][0] = wr[0];
            af[mt][ks][1] = wr[8 * OWB_STRIDE];
            af[mt][ks][2] = wr[4];
            af[mt][ks][3] = wr[8 * OWB_STRIDE + 4];
        }

    const float* xb2 = x + (size_t)b * CC * NN;
    float*       ob2 = out + (size_t)b * CC * NN;
#pragma unroll
    for (int nt2 = 0; nt2 < 2; nt2++) {
        const int qb = wid * 16 + nt2 * 8;
        const uint* br = attB + (size_t)(qb + g) * ATTB_STRIDE + tig;
        uint b00 = br[0], b01 = br[4], b10 = br[8], b11 = br[12];
        const float s0 = scS[qb + 2 * tig];
        const float s1 = scS[qb + 2 * tig + 1];
        const int qg = tile * 512 + qb + 2 * tig;
#pragma unroll
        for (int mt = 0; mt < 4; mt++) {
            float c[4] = {0.f, 0.f, 0.f, 0.f};
            mma_16n8k16(c, af[mt][0], b00, b01);
            mma_16n8k16(c, af[mt][1], b10, b11);
            const int ch0 = mt * 16 + g;
            float2 x0 = *(const float2*)(xb2 + (size_t)ch0 * NN + qg);
            float2 x1 = *(const float2*)(xb2 + (size_t)(ch0 + 8) * NN + qg);
            *(float2*)(ob2 + (size_t)ch0 * NN + qg) =
                make_float2(fmaf(c[0], s0, x0.x), fmaf(c[1], s1, x0.y));
            *(float2*)(ob2 + (size_t)(ch0 + 8) * NN + qg) =
                make_float2(fmaf(c[2], s0, x1.x), fmaf(c[3], s1, x1.y));
        }
    }
}

// =========================================================================
extern "C" void kernel_launch(void* const* d_in, const int* in_sizes, int n_in,
                              void* d_out, int out_size)
{
    const float* x     = (const float*)d_in[0];
    const float* tw    = (const float*)d_in[1];
    const float* pw    = (const float*)d_in[2];
    const float* gw    = (const float*)d_in[3];
    const float* ow    = (const float*)d_in[4];
    const float* gamma = (const float*)d_in[5];
    float* out = (float*)d_out;

    cudaFuncSetAttribute(attn_kernel,
                         cudaFuncAttributeMaxDynamicSharedMemorySize, SMEM_BYTES);

    proj_kernel<<<BB * NP / 128, 256>>>(x, tw, pw, gw);
    attn_kernel<<<dim3(8, BB), THREADS, SMEM_BYTES>>>(x, ow, gamma, out);
}